// round 1
// baseline (speedup 1.0000x reference)
#include <cuda_runtime.h>
#include <math.h>

#define NPRE   131264      // 192 + 131072
#define NQ     128
#define DDIM   768
#define BSZ    64
#define NTILE  128
#define KTILES 48          // 768 / 16

// ---------------- device scratch (static: no allocation) ----------------
__device__ float    g_pnorm[NPRE];
__device__ float    g_pscore[NPRE];
__device__ float    g_plab[NPRE];
__device__ float    g_U[NQ];
__device__ float    g_Bu[NQ];
__device__ float    g_Lu[NQ];
__device__ float    g_Lsum;
__device__ int      g_cnt[NQ];
__device__ unsigned g_mn[NQ];
__device__ unsigned g_mx[NQ];

// order-preserving float<->uint encode for atomicMin/Max
__device__ __forceinline__ unsigned fenc(float f){
    unsigned u = __float_as_uint(f);
    return (u & 0x80000000u) ? ~u : (u | 0x80000000u);
}
__device__ __forceinline__ float fdec(unsigned e){
    return (e & 0x80000000u) ? __uint_as_float(e & 0x7FFFFFFFu)
                             : __uint_as_float(~e);
}

// ---------------- kernel 0: reset accumulators (every replay) ----------------
__global__ void lpe_init_kernel(){
    int i = threadIdx.x;
    if (i < NQ){
        g_U[i] = 0.f; g_Bu[i] = 0.f; g_Lu[i] = 0.f; g_cnt[i] = 0;
        g_mn[i] = 0xFFFFFFFFu;   // encodes "+inf"
        g_mx[i] = 0u;            // encodes "-inf"
    }
    if (i == 0) g_Lsum = 0.f;
}

// ---------------- kernel 1: per-row norm, score, label (one warp/row) ----------------
__global__ void lpe_prep_kernel(const float* __restrict__ vl,
                                const float* __restrict__ score,
                                const float* __restrict__ itm,
                                const float* __restrict__ queue,
                                const float* __restrict__ qlab,
                                const float* __restrict__ W,
                                const float* __restrict__ bias){
    int w    = (blockIdx.x * blockDim.x + threadIdx.x) >> 5;
    int lane = threadIdx.x & 31;
    if (w >= NPRE) return;
    bool isq = (w >= 192);
    const float* src = isq ? (queue + (size_t)(w - 192) * DDIM)
                           : (vl    + (size_t)w * DDIM);
    float ss = 0.f, l0 = 0.f, l1 = 0.f;
#pragma unroll
    for (int it = 0; it < 6; it++){
        int k = (it * 32 + lane) * 4;
        float4 v = *(const float4*)(src + k);
        ss += v.x*v.x + v.y*v.y + v.z*v.z + v.w*v.w;
        if (isq){
            // W row-major (768,2): W[k][c] = W[2k+c]
            float4 w0 = *(const float4*)(W + k*2);       // k, k+1
            float4 w1 = *(const float4*)(W + k*2 + 4);   // k+2, k+3
            l0 += v.x*w0.x + v.y*w0.z + v.z*w1.x + v.w*w1.z;
            l1 += v.x*w0.y + v.y*w0.w + v.z*w1.y + v.w*w1.w;
        }
    }
#pragma unroll
    for (int d = 16; d; d >>= 1){
        ss += __shfl_down_sync(0xFFFFFFFFu, ss, d);
        l0 += __shfl_down_sync(0xFFFFFFFFu, l0, d);
        l1 += __shfl_down_sync(0xFFFFFFFFu, l1, d);
    }
    if (lane == 0){
        g_pnorm[w]  = sqrtf(ss);
        // softmax([l0,l1])[1] = sigmoid(l1-l0)
        g_pscore[w] = isq ? 1.f / (1.f + expf((l0 + bias[0]) - (l1 + bias[1])))
                          : score[w];
        float lb = isq ? qlab[w - 192] : itm[w];
        g_plab[w] = lb;
        atomicAdd(&g_Lsum, lb);
    }
}

// ---------------- kernel 2: fused GEMM + filtered statistics ----------------
__global__ __launch_bounds__(256, 2)
void lpe_main_kernel(const float* __restrict__ vl,
                     const float* __restrict__ score,
                     const float* __restrict__ queue){
    __shared__ float As[2][16][132];
    __shared__ float Bs[2][16][132];
    __shared__ float pn_s[NTILE], ps_s[NTILE], pl_s[NTILE];
    __shared__ float qn_s[NQ],    qs_s[NQ];

    const float* q = vl + (size_t)BSZ * DDIM;   // q rows = vl rows 64..191
    int n_base = blockIdx.x * NTILE;
    int tid = threadIdx.x;
    int tx  = tid & 15;     // pre-row micro dim
    int ty  = tid >> 4;     // q-row micro dim

    if (tid < NTILE){
        int jg = n_base + tid;
        if (jg < NPRE){
            pn_s[tid] = g_pnorm[jg];
            ps_s[tid] = g_pscore[jg];
            pl_s[tid] = g_plab[jg];
        } else {
            pn_s[tid] = 1.f; ps_s[tid] = 0.f; pl_s[tid] = 0.f;
        }
        qn_s[tid] = g_pnorm[BSZ + tid];
        qs_s[tid] = score[BSZ + tid];
    }

    // loader mapping: 256 threads x 2 float4 per matrix per chunk
    int row0 = tid >> 2;         // 0..63
    int row1 = row0 + 64;        // 64..127
    int kq   = (tid & 3) << 2;   // 0,4,8,12

    const float* aptr0 = q + (size_t)row0 * DDIM + kq;
    const float* aptr1 = q + (size_t)row1 * DDIM + kq;
    int jg0 = n_base + row0, jg1 = n_base + row1;
    const float* bptr0 = (jg0 < 192) ? (vl + (size_t)jg0 * DDIM + kq)
                       : (jg0 < NPRE ? (queue + (size_t)(jg0 - 192) * DDIM + kq)
                                     : (const float*)0);
    const float* bptr1 = (jg1 < 192) ? (vl + (size_t)jg1 * DDIM + kq)
                       : (jg1 < NPRE ? (queue + (size_t)(jg1 - 192) * DDIM + kq)
                                     : (const float*)0);

    float acc[8][8];
#pragma unroll
    for (int i = 0; i < 8; i++)
#pragma unroll
        for (int j = 0; j < 8; j++) acc[i][j] = 0.f;

    float4 ra0, ra1, rb0, rb1;
    const float4 z4 = make_float4(0.f, 0.f, 0.f, 0.f);

#define LPE_LOADG(cc) do{ int _off = (cc) * 16;                               \
        ra0 = *(const float4*)(aptr0 + _off);                                 \
        ra1 = *(const float4*)(aptr1 + _off);                                 \
        rb0 = bptr0 ? *(const float4*)(bptr0 + _off) : z4;                    \
        rb1 = bptr1 ? *(const float4*)(bptr1 + _off) : z4;                    \
    }while(0)

#define LPE_STORE(nb) do{                                                     \
        As[nb][kq+0][row0]=ra0.x; As[nb][kq+1][row0]=ra0.y;                   \
        As[nb][kq+2][row0]=ra0.z; As[nb][kq+3][row0]=ra0.w;                   \
        As[nb][kq+0][row1]=ra1.x; As[nb][kq+1][row1]=ra1.y;                   \
        As[nb][kq+2][row1]=ra1.z; As[nb][kq+3][row1]=ra1.w;                   \
        Bs[nb][kq+0][row0]=rb0.x; Bs[nb][kq+1][row0]=rb0.y;                   \
        Bs[nb][kq+2][row0]=rb0.z; Bs[nb][kq+3][row0]=rb0.w;                   \
        Bs[nb][kq+0][row1]=rb1.x; Bs[nb][kq+1][row1]=rb1.y;                   \
        Bs[nb][kq+2][row1]=rb1.z; Bs[nb][kq+3][row1]=rb1.w;                   \
    }while(0)

    LPE_LOADG(0);
    LPE_STORE(0);
    __syncthreads();

    int cur = 0;
#pragma unroll 1
    for (int c = 0; c < KTILES; c++){
        bool more = (c + 1 < KTILES);
        if (more) LPE_LOADG(c + 1);

#pragma unroll
        for (int kk = 0; kk < 16; kk++){
            float a[8], b[8];
            *(float4*)(a)     = *(const float4*)&As[cur][kk][ty * 8];
            *(float4*)(a + 4) = *(const float4*)&As[cur][kk][ty * 8 + 4];
            *(float4*)(b)     = *(const float4*)&Bs[cur][kk][tx * 8];
            *(float4*)(b + 4) = *(const float4*)&Bs[cur][kk][tx * 8 + 4];
#pragma unroll
            for (int i = 0; i < 8; i++)
#pragma unroll
                for (int j = 0; j < 8; j++)
                    acc[i][j] = fmaf(a[i], b[j], acc[i][j]);
        }
        __syncthreads();
        if (more) LPE_STORE(cur ^ 1);
        __syncthreads();
        cur ^= 1;
    }

    // ---- epilogue: filtered-stat accumulation; filtered entries need nothing ----
#pragma unroll 1
    for (int i = 0; i < 8; i++){
        int m = ty * 8 + i;                 // q row
        float qni = qn_s[m], qsi = qs_s[m];
        float U = 0.f, Bu = 0.f, Lu = 0.f;
        float mn = 3.4e38f, mx = -3.4e38f;
        int cnt = 0;
#pragma unroll
        for (int j = 0; j < 8; j++){
            int r  = tx * 8 + j;
            int jg = n_base + r;
            if (jg < NPRE){
                float np  = qni * pn_s[r];
                float cosv = acc[i][j] / fmaxf(np, 1e-8f);
                if (cosv >= 0.5f){
                    float d   = ps_s[r] - qsi;
                    float sim = cosv * (1.f - d * d);
                    float lb  = pl_s[r];
                    cnt++; U += sim; Bu += sim * lb; Lu += lb;
                    mn = fminf(mn, sim); mx = fmaxf(mx, sim);
                }
            }
        }
        // reduce across the 16 lanes sharing this q row (one half-warp)
#pragma unroll
        for (int d = 8; d; d >>= 1){
            U   += __shfl_down_sync(0xFFFFFFFFu, U,  d);
            Bu  += __shfl_down_sync(0xFFFFFFFFu, Bu, d);
            Lu  += __shfl_down_sync(0xFFFFFFFFu, Lu, d);
            cnt += __shfl_down_sync(0xFFFFFFFFu, cnt, d);
            mn   = fminf(mn, __shfl_down_sync(0xFFFFFFFFu, mn, d));
            mx   = fmaxf(mx, __shfl_down_sync(0xFFFFFFFFu, mx, d));
        }
        if (tx == 0 && cnt > 0){
            atomicAdd(&g_cnt[m], cnt);
            atomicAdd(&g_U[m],  U);
            atomicAdd(&g_Bu[m], Bu);
            atomicAdd(&g_Lu[m], Lu);
            atomicMin(&g_mn[m], fenc(mn));
            atomicMax(&g_mx[m], fenc(mx));
        }
    }
#undef LPE_LOADG
#undef LPE_STORE
}

// ---------------- kernel 3: closed-form outputs ----------------
__global__ void lpe_final_kernel(float* __restrict__ out, int has_gamma){
    int i = threadIdx.x;
    int wbase = has_gamma ? 385 : 384;
    if (i < BSZ){
        out[i]         = 1.f;   // exp_itm_label[0:64]
        out[192 + i]   = 1.f;   // exp_wo_alter_label[0:64]
        out[wbase + i] = 0.f;   // weights[0:64]
    }
    if (has_gamma && i == 0) out[384] = 1.0f;   // gamma = 131264/131264
    if (i < NQ){
        int   c  = g_cnt[i];
        float U  = g_U[i], Bu = g_Bu[i], Lu = g_Lu[i], Ls = g_Lsum;
        float smin, smax;
        if (c == 0){ smin = -1.f; smax = -1.f; }
        else {
            float mnU = fdec(g_mn[i]), mxU = fdec(g_mx[i]);
            if (c < NPRE){ smin = fminf(-1.f, mnU); smax = fmaxf(-1.f, mxU); }
            else         { smin = mnU;             smax = mxU; }
        }
        float nf = (float)(NPRE - c);
        // cancellation-free decompositions of the row reductions
        float S  = nf * (-1.f - smin) + (U - (float)c * smin);
        float T  = (-1.f - smin) * (Ls - Lu) + (Bu - smin * Lu);
        float R  = smax - smin + 1e-8f;
        float wo = T / (S + 1e-8f * R);
        float alt = fmaxf(wo, 0.f);
        float w   = (c != 0) ? U / (float)c : 0.f;
        float wt  = fmaxf(w - 0.5f, 0.f) * 2.0f;   // clip(w-0.5,0)/(1-0.5)
        out[BSZ + i]         = alt;
        out[192 + BSZ + i]   = wo;
        out[wbase + BSZ + i] = wt;
    }
}

// ---------------- launch ----------------
extern "C" void kernel_launch(void* const* d_in, const int* in_sizes, int n_in,
                              void* d_out, int out_size){
    const float* vl    = (const float*)d_in[0];
    const float* score = (const float*)d_in[1];
    const float* itm   = (const float*)d_in[2];
    const float* queue = (const float*)d_in[3];
    const float* qlab  = (const float*)d_in[4];
    const float* W     = (const float*)d_in[5];
    const float* bias  = (const float*)d_in[6];
    float* out = (float*)d_out;
    (void)in_sizes; (void)n_in;

    lpe_init_kernel<<<1, 128>>>();
    lpe_prep_kernel<<<NPRE / 8, 256>>>(vl, score, itm, queue, qlab, W, bias);
    lpe_main_kernel<<<(NPRE + NTILE - 1) / NTILE, 256>>>(vl, score, queue);
    lpe_final_kernel<<<1, 192>>>(out, (out_size >= 577) ? 1 : 0);
}

// round 2
// speedup vs baseline: 3.9532x; 3.9532x over previous
#include <cuda_runtime.h>
#include <cuda_bf16.h>
#include <math.h>
#include <stdint.h>

#define NPRE   131264      // 192 + 131072
#define NQ     128
#define DDIM   768
#define BSZ    64
#define NTILE  128
#define KC     32          // K chunk
#define NCH    24          // 768 / 32
#define SLD    40          // smem row stride in bf16 elems (32 + 8 pad)
#define NBLK   ((NPRE + NTILE - 1) / NTILE)   // 1026

// ---------------- device scratch (static: no allocation) ----------------
__device__ float    g_U[NQ];
__device__ float    g_Bu[NQ];
__device__ float    g_Lu[NQ];
__device__ float    g_Lsum;
__device__ int      g_cnt[NQ];
__device__ unsigned g_mn[NQ];
__device__ unsigned g_mx[NQ];

// order-preserving float<->uint encode for atomicMin/Max
__device__ __forceinline__ unsigned fenc(float f){
    unsigned u = __float_as_uint(f);
    return (u & 0x80000000u) ? ~u : (u | 0x80000000u);
}
__device__ __forceinline__ float fdec(unsigned e){
    return (e & 0x80000000u) ? __uint_as_float(e & 0x7FFFFFFFu)
                             : __uint_as_float(~e);
}

// ---------------- dynamic shared layout ----------------
struct SmemLayout {
    __nv_bfloat16 A[2][NTILE * SLD];
    __nv_bfloat16 B[2][NTILE * SLD];
    float W[DDIM * 2];
    float pl[NTILE], pn[NTILE], ps[NTILE], qn[NQ], qs[NQ];
    float rA[NTILE], rB[NTILE], rl0[NTILE], rl1[NTILE];
    float U[NQ], Bu[NQ], Lu[NQ];
    int   C[NQ];
    unsigned Mn[NQ], Mx[NQ];
};

// ---------------- kernel 0: reset accumulators (every replay) ----------------
__global__ void lpe_init_kernel(){
    int i = threadIdx.x;
    if (i < NQ){
        g_U[i] = 0.f; g_Bu[i] = 0.f; g_Lu[i] = 0.f; g_cnt[i] = 0;
        g_mn[i] = 0xFFFFFFFFu;   // +inf encoded
        g_mx[i] = 0u;            // -inf encoded
    }
    if (i == 0) g_Lsum = 0.f;
}

// ---------------- kernel 1: label sum (tiny) ----------------
__global__ void lpe_lsum_kernel(const float* __restrict__ itm,
                                const float* __restrict__ qlab){
    float v = 0.f;
    for (int i = blockIdx.x * blockDim.x + threadIdx.x; i < NPRE;
         i += gridDim.x * blockDim.x)
        v += (i < 192) ? itm[i] : qlab[i - 192];
#pragma unroll
    for (int d = 16; d; d >>= 1) v += __shfl_down_sync(0xFFFFFFFFu, v, d);
    if ((threadIdx.x & 31) == 0) atomicAdd(&g_Lsum, v);
}

// ---------------- MMA helpers ----------------
__device__ __forceinline__ void ldsm4(uint32_t &r0, uint32_t &r1,
                                      uint32_t &r2, uint32_t &r3, uint32_t a){
    asm volatile("ldmatrix.sync.aligned.m8n8.x4.shared.b16 {%0,%1,%2,%3},[%4];"
        : "=r"(r0), "=r"(r1), "=r"(r2), "=r"(r3) : "r"(a));
}
__device__ __forceinline__ void mma16816(float* c, const uint32_t* a,
                                         const uint32_t* b){
    asm volatile("mma.sync.aligned.m16n8k16.row.col.f32.bf16.bf16.f32 "
        "{%0,%1,%2,%3},{%4,%5,%6,%7},{%8,%9},{%0,%1,%2,%3};"
        : "+f"(c[0]), "+f"(c[1]), "+f"(c[2]), "+f"(c[3])
        : "r"(a[0]), "r"(a[1]), "r"(a[2]), "r"(a[3]), "r"(b[0]), "r"(b[1]));
}
// convert float4 -> 4 bf16 (packed uint2) and accumulate sum-of-squares of the
// ROUNDED values (keeps cos_self == 1 self-consistent with the bf16 MMA)
__device__ __forceinline__ uint2 pack_ss(float4 v, float& ss){
    uint32_t lo, hi;
    asm("cvt.rn.bf16x2.f32 %0, %1, %2;" : "=r"(lo) : "f"(v.y), "f"(v.x));
    asm("cvt.rn.bf16x2.f32 %0, %1, %2;" : "=r"(hi) : "f"(v.w), "f"(v.z));
    float a0 = __uint_as_float(lo << 16);
    float a1 = __uint_as_float(lo & 0xFFFF0000u);
    float a2 = __uint_as_float(hi << 16);
    float a3 = __uint_as_float(hi & 0xFFFF0000u);
    ss = fmaf(a0, a0, fmaf(a1, a1, fmaf(a2, a2, fmaf(a3, a3, ss))));
    return make_uint2(lo, hi);
}
__device__ __forceinline__ uint32_t sptr(const void* p){
    return (uint32_t)__cvta_generic_to_shared(p);
}

// ---------------- kernel 2: fused bf16-MMA GEMM + norms + stats ----------------
__global__ __launch_bounds__(256)
void lpe_main_kernel(const float* __restrict__ vl,
                     const float* __restrict__ score,
                     const float* __restrict__ queue,
                     const float* __restrict__ itm,
                     const float* __restrict__ qlab,
                     const float* __restrict__ W,
                     const float* __restrict__ bias){
    extern __shared__ char smem_raw[];
    SmemLayout& S = *reinterpret_cast<SmemLayout*>(smem_raw);

    const int tid  = threadIdx.x;
    const int lane = tid & 31;
    const int wid  = tid >> 5;
    const int n_base = blockIdx.x * NTILE;

    // ---- init smem: labels, stats, W ----
    if (tid < NTILE){
        int jg = n_base + tid;
        S.pl[tid] = (jg < 192) ? itm[jg] : (jg < NPRE ? qlab[jg - 192] : 0.f);
        S.U[tid] = 0.f; S.Bu[tid] = 0.f; S.Lu[tid] = 0.f; S.C[tid] = 0;
        S.Mn[tid] = 0xFFFFFFFFu; S.Mx[tid] = 0u;
        S.qs[tid] = score[BSZ + tid];
    }
    for (int i = tid; i < DDIM * 2; i += 256) S.W[i] = W[i];

    // ---- loader mapping: 2 threads per row, 4 float4 each per matrix ----
    const int row = tid >> 1;        // 0..127
    const int hf  = tid & 1;         // which 16-col half of the 32-col chunk
    const int rowOff = row * SLD + hf * 16;
    const float* aSrc = vl + (size_t)(BSZ + row) * DDIM + hf * 16;
    const int jg = n_base + row;
    const bool bValid = (jg < NPRE);
    const float* bSrc = (jg < 192) ? (vl + (size_t)jg * DDIM + hf * 16)
                      : (bValid    ? (queue + (size_t)(jg - 192) * DDIM + hf * 16)
                                   : aSrc);

    float ssA = 0.f, ssB = 0.f, l0 = 0.f, l1 = 0.f;
    float4 fA[4], fB[4];

    // ---- MMA thread mapping: 8 warps = 2 (M) x 4 (N) ----
    const int wm = wid & 1;          // M block of 64
    const int wn = wid >> 1;         // N block of 32
    const int aRow = wm * 64 + (lane & 15);
    const int aK   = (lane >> 4) * 8;
    const int bRow = wn * 32 + (lane & 7) + ((lane >> 4) << 3);
    const int bK   = ((lane >> 3) & 1) * 8;
    uint32_t aBase[2], bBase[2];
#pragma unroll
    for (int b = 0; b < 2; b++){
        aBase[b] = sptr(&S.A[b][0]) + (uint32_t)(aRow * SLD + aK) * 2u;
        bBase[b] = sptr(&S.B[b][0]) + (uint32_t)(bRow * SLD + bK) * 2u;
    }

    float acc[4][4][4];
#pragma unroll
    for (int i = 0; i < 4; i++)
#pragma unroll
        for (int j = 0; j < 4; j++)
#pragma unroll
            for (int r = 0; r < 4; r++) acc[i][j][r] = 0.f;

#define LPE_LDG(c) do{                                                        \
        const float* _pa = aSrc + (c) * KC;                                   \
        _Pragma("unroll")                                                     \
        for (int _i = 0; _i < 4; _i++) fA[_i] = *(const float4*)(_pa + _i*4); \
        if (bValid){                                                          \
            const float* _pb = bSrc + (c) * KC;                               \
            _Pragma("unroll")                                                 \
            for (int _i = 0; _i < 4; _i++) fB[_i] = *(const float4*)(_pb + _i*4); \
        } else {                                                              \
            _Pragma("unroll")                                                 \
            for (int _i = 0; _i < 4; _i++) fB[_i] = make_float4(0,0,0,0);     \
        }                                                                     \
    }while(0)

#define LPE_STS(buf, c) do{                                                   \
        _Pragma("unroll")                                                     \
        for (int _i = 0; _i < 4; _i++){                                       \
            uint2 _pa = pack_ss(fA[_i], ssA);                                 \
            *(uint2*)&S.A[buf][rowOff + _i*4] = _pa;                          \
            uint2 _pb = pack_ss(fB[_i], ssB);                                 \
            *(uint2*)&S.B[buf][rowOff + _i*4] = _pb;                          \
            int _kg = (c) * KC + hf * 16 + _i * 4;                            \
            float4 _w01 = *(const float4*)&S.W[2*_kg];                        \
            float4 _w23 = *(const float4*)&S.W[2*_kg + 4];                    \
            l0 = fmaf(fB[_i].x,_w01.x, fmaf(fB[_i].y,_w01.z,                  \
                 fmaf(fB[_i].z,_w23.x, fmaf(fB[_i].w,_w23.z, l0))));          \
            l1 = fmaf(fB[_i].x,_w01.y, fmaf(fB[_i].y,_w01.w,                  \
                 fmaf(fB[_i].z,_w23.y, fmaf(fB[_i].w,_w23.w, l1))));          \
        }                                                                     \
    }while(0)

#define LPE_COMPUTE(cur) do{                                                  \
        _Pragma("unroll")                                                     \
        for (int ks = 0; ks < 2; ks++){                                       \
            uint32_t a[4][4], bb[4][2];                                       \
            _Pragma("unroll")                                                 \
            for (int mi = 0; mi < 4; mi++)                                    \
                ldsm4(a[mi][0], a[mi][1], a[mi][2], a[mi][3],                 \
                      aBase[cur] + (uint32_t)((mi*16*SLD + ks*16) * 2));      \
            { uint32_t t0,t1,t2,t3;                                           \
              ldsm4(t0,t1,t2,t3, bBase[cur] + (uint32_t)(ks*32));             \
              bb[0][0]=t0; bb[0][1]=t1; bb[1][0]=t2; bb[1][1]=t3; }           \
            { uint32_t t0,t1,t2,t3;                                           \
              ldsm4(t0,t1,t2,t3, bBase[cur] + (uint32_t)((16*SLD+ks*16)*2));  \
              bb[2][0]=t0; bb[2][1]=t1; bb[3][0]=t2; bb[3][1]=t3; }           \
            _Pragma("unroll")                                                 \
            for (int mi = 0; mi < 4; mi++)                                    \
                _Pragma("unroll")                                             \
                for (int nj = 0; nj < 4; nj++)                                \
                    mma16816(acc[mi][nj], a[mi], bb[nj]);                     \
        }                                                                     \
    }while(0)

    LPE_LDG(0);
    __syncthreads();          // W/labels/stats visible
    LPE_STS(0, 0);
    __syncthreads();          // tiles ready

    int cur = 0;
#pragma unroll 1
    for (int c = 0; c < NCH; c++){
        bool more = (c + 1 < NCH);
        if (more) LPE_LDG(c + 1);
        LPE_COMPUTE(cur);
        if (more) LPE_STS(cur ^ 1, c + 1);
        __syncthreads();
        cur ^= 1;
    }

    // ---- reduce norms / logits (2 partials per row) ----
    if (hf == 0){ S.rA[row] = ssA; S.rB[row] = ssB; S.rl0[row] = l0; S.rl1[row] = l1; }
    __syncthreads();
    if (hf == 1){
        S.qn[row] = sqrtf(S.rA[row] + ssA);
        S.pn[row] = sqrtf(S.rB[row] + ssB);
        float L0 = S.rl0[row] + l0 + bias[0];
        float L1 = S.rl1[row] + l1 + bias[1];
        S.ps[row] = (jg < 192) ? score[jg] : 1.f / (1.f + expf(L0 - L1));
    }
    __syncthreads();

    // ---- epilogue: filter + rare stats (filtered entries contribute nothing) ----
    const int grp = lane >> 2, qd = lane & 3;
#pragma unroll
    for (int mi = 0; mi < 4; mi++){
#pragma unroll
        for (int r2 = 0; r2 < 2; r2++){
            int m = wm * 64 + mi * 16 + grp + r2 * 8;
            float qn = S.qn[m], qsv = S.qs[m];
#pragma unroll
            for (int nj = 0; nj < 4; nj++){
#pragma unroll
                for (int c01 = 0; c01 < 2; c01++){
                    int n = wn * 32 + nj * 8 + qd * 2 + c01;
                    float v = acc[mi][nj][r2 * 2 + c01];
                    float t = fmaxf(qn * S.pn[n], 1e-8f);
                    if (v >= 0.5f * t){
                        float cosv = v / t;
                        float d = S.ps[n] - qsv;
                        float sim = cosv * (1.f - d * d);
                        float lb = S.pl[n];
                        atomicAdd(&S.U[m], sim);
                        atomicAdd(&S.Bu[m], sim * lb);
                        atomicAdd(&S.Lu[m], lb);
                        atomicAdd(&S.C[m], 1);
                        atomicMin(&S.Mn[m], fenc(sim));
                        atomicMax(&S.Mx[m], fenc(sim));
                    }
                }
            }
        }
    }
    __syncthreads();

    // ---- flush to global (only rows that saw unfiltered entries) ----
    if (tid < NQ && S.C[tid] > 0){
        atomicAdd(&g_cnt[tid], S.C[tid]);
        atomicAdd(&g_U[tid],  S.U[tid]);
        atomicAdd(&g_Bu[tid], S.Bu[tid]);
        atomicAdd(&g_Lu[tid], S.Lu[tid]);
        atomicMin(&g_mn[tid], S.Mn[tid]);
        atomicMax(&g_mx[tid], S.Mx[tid]);
    }
#undef LPE_LDG
#undef LPE_STS
#undef LPE_COMPUTE
}

// ---------------- kernel 3: closed-form outputs ----------------
__global__ void lpe_final_kernel(float* __restrict__ out, int has_gamma){
    int i = threadIdx.x;
    int wbase = has_gamma ? 385 : 384;
    if (i < BSZ){
        out[i]         = 1.f;
        out[192 + i]   = 1.f;
        out[wbase + i] = 0.f;
    }
    if (has_gamma && i == 0) out[384] = 1.0f;   // gamma = 131264/131264
    if (i < NQ){
        int   c  = g_cnt[i];
        float U  = g_U[i], Bu = g_Bu[i], Lu = g_Lu[i], Ls = g_Lsum;
        float smin, smax;
        if (c == 0){ smin = -1.f; smax = -1.f; }
        else {
            float mnU = fdec(g_mn[i]), mxU = fdec(g_mx[i]);
            if (c < NPRE){ smin = fminf(-1.f, mnU); smax = fmaxf(-1.f, mxU); }
            else         { smin = mnU;             smax = mxU; }
        }
        float nf = (float)(NPRE - c);
        float Sv = nf * (-1.f - smin) + (U - (float)c * smin);
        float T  = (-1.f - smin) * (Ls - Lu) + (Bu - smin * Lu);
        float R  = smax - smin + 1e-8f;
        float wo = T / (Sv + 1e-8f * R);
        float alt = fmaxf(wo, 0.f);
        float w   = (c != 0) ? U / (float)c : 0.f;
        float wt  = fmaxf(w - 0.5f, 0.f) * 2.0f;
        out[BSZ + i]         = alt;
        out[192 + BSZ + i]   = wo;
        out[wbase + BSZ + i] = wt;
    }
}

// ---------------- launch ----------------
extern "C" void kernel_launch(void* const* d_in, const int* in_sizes, int n_in,
                              void* d_out, int out_size){
    const float* vl    = (const float*)d_in[0];
    const float* score = (const float*)d_in[1];
    const float* itm   = (const float*)d_in[2];
    const float* queue = (const float*)d_in[3];
    const float* qlab  = (const float*)d_in[4];
    const float* W     = (const float*)d_in[5];
    const float* bias  = (const float*)d_in[6];
    float* out = (float*)d_out;
    (void)in_sizes; (void)n_in;

    static int smem_set = 0;
    const int smem_bytes = (int)sizeof(SmemLayout);
    if (!smem_set){
        cudaFuncSetAttribute(lpe_main_kernel,
                             cudaFuncAttributeMaxDynamicSharedMemorySize,
                             smem_bytes);
        smem_set = 1;
    }

    lpe_init_kernel<<<1, 128>>>();
    lpe_lsum_kernel<<<64, 256>>>(itm, qlab);
    lpe_main_kernel<<<NBLK, 256, smem_bytes>>>(vl, score, queue, itm, qlab, W, bias);
    lpe_final_kernel<<<1, 192>>>(out, (out_size >= 577) ? 1 : 0);
}